// round 4
// baseline (speedup 1.0000x reference)
#include <cuda_runtime.h>
#include <cuda_bf16.h>
#include <cstdint>

#define KN 131072
#define KK 16
#define KM 128
#define KD 64
#define BN 128   // n-rows per CTA (8 warps x 16 rows)

// Pre-split, fragment-arranged 'a':
// u32 index = (((k*4 + ks)*16 + mt)*32 + lane)*4 + c
//   c0,c1 = hi split (r=0: d0, r=1: d0+8), c2,c3 = lo split
// One uint4 per (k,ks,mt,lane) = both MMA B-operand regs for hi AND lo.
__device__ __align__(16) uint32_t g_b[KK * 8192];   // 512 KB, L2-resident

__device__ __forceinline__ uint32_t pack_bf(__nv_bfloat16 a, __nv_bfloat16 b) {
    return (uint32_t)__bfloat16_as_ushort(a) | ((uint32_t)__bfloat16_as_ushort(b) << 16);
}

__global__ void prep(const float* __restrict__ a) {
    int idx = blockIdx.x * 256 + threadIdx.x;   // 0 .. 131071
    int c  = idx & 3;
    int l  = (idx >> 2) & 31;
    int mt = (idx >> 7) & 15;
    int ks = (idx >> 11) & 3;
    int k  = idx >> 13;
    int r  = c & 1, sp = c >> 1;
    int m  = mt * 8 + (l >> 2);
    int d0 = ks * 16 + (l & 3) * 2 + r * 8;
    const float* am = a + ((size_t)k * KM + m) * KD + d0;
    float v0 = am[0], v1 = am[1];
    __nv_bfloat16 h0 = __float2bfloat16(v0), h1 = __float2bfloat16(v1);
    uint32_t o;
    if (sp == 0) {
        o = pack_bf(h0, h1);
    } else {
        o = pack_bf(__float2bfloat16(v0 - __bfloat162float(h0)),
                    __float2bfloat16(v1 - __bfloat162float(h1)));
    }
    g_b[idx] = o;
}

__device__ __forceinline__ void mma16816(float (&c)[4], const uint32_t (&A)[4],
                                         uint32_t b0, uint32_t b1) {
    asm volatile(
        "mma.sync.aligned.m16n8k16.row.col.f32.bf16.bf16.f32 "
        "{%0,%1,%2,%3}, {%4,%5,%6,%7}, {%8,%9}, {%0,%1,%2,%3};"
        : "+f"(c[0]), "+f"(c[1]), "+f"(c[2]), "+f"(c[3])
        : "r"(A[0]), "r"(A[1]), "r"(A[2]), "r"(A[3]), "r"(b0), "r"(b1));
}

__global__ __launch_bounds__(256, 3)
void madk3(const float* __restrict__ x, const float* __restrict__ s,
           const float* __restrict__ b, float* __restrict__ out)
{
    const int tid = threadIdx.x;
    const int w = tid >> 5, l = tid & 31;
    const int g = l >> 2, q = l & 3;
    const int row0 = blockIdx.x * BN + w * 16 + g;   // this thread's first n-row

    // ---- A fragments (hi/lo bf16 split) straight from gmem; reused for all 16 experts ----
    uint32_t Ahi[4][4], Alo[4][4];
    #pragma unroll
    for (int ks = 0; ks < 4; ++ks) {
        #pragma unroll
        for (int h = 0; h < 2; ++h) {
            int d = ks * 16 + q * 2 + h * 8;
            float2 v0 = __ldg((const float2*)(x + (size_t)row0 * KD + d));
            float2 v1 = __ldg((const float2*)(x + (size_t)(row0 + 8) * KD + d));
            __nv_bfloat16 h00 = __float2bfloat16(v0.x), h01 = __float2bfloat16(v0.y);
            __nv_bfloat16 h10 = __float2bfloat16(v1.x), h11 = __float2bfloat16(v1.y);
            Ahi[ks][h * 2 + 0] = pack_bf(h00, h01);
            Ahi[ks][h * 2 + 1] = pack_bf(h10, h11);
            Alo[ks][h * 2 + 0] = pack_bf(__float2bfloat16(v0.x - __bfloat162float(h00)),
                                         __float2bfloat16(v0.y - __bfloat162float(h01)));
            Alo[ks][h * 2 + 1] = pack_bf(__float2bfloat16(v1.x - __bfloat162float(h10)),
                                         __float2bfloat16(v1.y - __bfloat162float(h11)));
        }
    }

    float res0 = 0.f, res1 = 0.f;

    #pragma unroll 1
    for (int k = 0; k < KK; ++k) {
        const uint4* gb = (const uint4*)g_b + ((size_t)k * 4 * 16 * 32) + l;
        const float* bk = b + k * KM;
        float s0 = 0.f, s1 = 0.f;

        #pragma unroll
        for (int ch = 0; ch < 4; ++ch) {
            float acc[4][4];
            #pragma unroll
            for (int mt = 0; mt < 4; ++mt)
                #pragma unroll
                for (int j = 0; j < 4; ++j) acc[mt][j] = 0.f;

            #pragma unroll
            for (int ks = 0; ks < 4; ++ks) {
                #pragma unroll
                for (int mt = 0; mt < 4; ++mt) {
                    // one LDG.128: both hi-regs and lo-regs of B for this (ks, mtile)
                    uint4 B = __ldg(gb + (size_t)(ks * 16 + ch * 4 + mt) * 32);
                    mma16816(acc[mt], Ahi[ks], B.x, B.y);   // hi*hi
                    mma16816(acc[mt], Ahi[ks], B.z, B.w);   // hi*lo
                    mma16816(acc[mt], Alo[ks], B.x, B.y);   // lo*hi
                }
            }

            // fused epilogue for this 32-column chunk (no max-sub: scores bounded)
            #pragma unroll
            for (int mt = 0; mt < 4; ++mt) {
                int m0 = (ch * 4 + mt) * 8 + q * 2;
                float2 bb = __ldg((const float2*)(bk + m0));
                s0 += __expf(acc[mt][0] + bb.x);
                s0 += __expf(acc[mt][1] + bb.y);
                s1 += __expf(acc[mt][2] + bb.x);
                s1 += __expf(acc[mt][3] + bb.y);
            }
        }

        // reduce exp-sums across the 4 lanes (q bits) sharing each n-row
        s0 += __shfl_xor_sync(0xffffffffu, s0, 1);
        s0 += __shfl_xor_sync(0xffffffffu, s0, 2);
        s1 += __shfl_xor_sync(0xffffffffu, s1, 1);
        s1 += __shfl_xor_sync(0xffffffffu, s1, 2);

        float sv = __ldg(s + k);
        res0 = fmaf(sv, __logf(s0), res0);
        res1 = fmaf(sv, __logf(s1), res1);
    }

    if (q == 0) {
        out[row0]     = res0;
        out[row0 + 8] = res1;
    }
}

extern "C" void kernel_launch(void* const* d_in, const int* in_sizes, int n_in,
                              void* d_out, int out_size)
{
    const float* x = (const float*)d_in[0];   // [131072, 64]
    const float* s = (const float*)d_in[1];   // [16]
    const float* a = (const float*)d_in[2];   // [16, 128, 64]
    const float* b = (const float*)d_in[3];   // [16, 128]
    float* out = (float*)d_out;

    prep<<<KK * 8192 / 256, 256>>>(a);
    madk3<<<KN / BN, 256>>>(x, s, b, out);
}

// round 5
// speedup vs baseline: 1.2396x; 1.2396x over previous
#include <cuda_runtime.h>
#include <cuda_bf16.h>
#include <cstdint>

#define KN 131072
#define KK 16
#define KM 128
#define KD 64
#define BN 128   // n-rows per CTA (8 warps x 16 rows)

// Pre-split, fragment-arranged 'a':
// u32 index = (((k*4 + ks)*16 + mt)*32 + lane)*4 + c
//   c0,c1 = hi-split B regs, c2,c3 = lo-split B regs  (one uint4 per (k,ks,mt,lane))
__device__ __align__(16) uint32_t g_b[KK * 8192];   // 512 KB, L2-resident

__device__ __forceinline__ uint32_t pack_bf(__nv_bfloat16 a, __nv_bfloat16 b) {
    return (uint32_t)__bfloat16_as_ushort(a) | ((uint32_t)__bfloat16_as_ushort(b) << 16);
}

__global__ void prep(const float* __restrict__ a) {
    int idx = blockIdx.x * 256 + threadIdx.x;   // 0 .. 131071
    int c  = idx & 3;
    int l  = (idx >> 2) & 31;
    int mt = (idx >> 7) & 15;
    int ks = (idx >> 11) & 3;
    int k  = idx >> 13;
    int r  = c & 1, sp = c >> 1;
    int m  = mt * 8 + (l >> 2);
    int d0 = ks * 16 + (l & 3) * 2 + r * 8;
    const float* am = a + ((size_t)k * KM + m) * KD + d0;
    float v0 = am[0], v1 = am[1];
    __nv_bfloat16 h0 = __float2bfloat16(v0), h1 = __float2bfloat16(v1);
    uint32_t o;
    if (sp == 0) {
        o = pack_bf(h0, h1);
    } else {
        o = pack_bf(__float2bfloat16(v0 - __bfloat162float(h0)),
                    __float2bfloat16(v1 - __bfloat162float(h1)));
    }
    g_b[idx] = o;
}

__device__ __forceinline__ void mma16816(float (&c)[4], const uint32_t (&A)[4],
                                         uint32_t b0, uint32_t b1) {
    asm volatile(
        "mma.sync.aligned.m16n8k16.row.col.f32.bf16.bf16.f32 "
        "{%0,%1,%2,%3}, {%4,%5,%6,%7}, {%8,%9}, {%0,%1,%2,%3};"
        : "+f"(c[0]), "+f"(c[1]), "+f"(c[2]), "+f"(c[3])
        : "r"(A[0]), "r"(A[1]), "r"(A[2]), "r"(A[3]), "r"(b0), "r"(b1));
}
__device__ __forceinline__ uint32_t smem_u32(const void* p) {
    uint32_t a;
    asm("{ .reg .u64 t; cvta.to.shared.u64 t, %1; cvt.u32.u64 %0, t; }" : "=r"(a) : "l"(p));
    return a;
}
__device__ __forceinline__ void cp16(uint32_t s, const void* g) {
    asm volatile("cp.async.cg.shared.global [%0], [%1], 16;" :: "r"(s), "l"(g));
}
#define CP_COMMIT() asm volatile("cp.async.commit_group;" ::: "memory")
#define CP_WAIT(n)  asm volatile("cp.async.wait_group %0;" :: "n"(n) : "memory")

#define TILE_BYTES 32768
#define DYN_SMEM   (3 * TILE_BYTES)   // 96 KB ring of a-tiles

__global__ __launch_bounds__(256, 2)
void madk5(const float* __restrict__ x, const float* __restrict__ s,
           const float* __restrict__ b, float* __restrict__ out)
{
    extern __shared__ __align__(16) char smem[];

    const int tid = threadIdx.x;
    const int w = tid >> 5, l = tid & 31;
    const int g = l >> 2, q = l & 3;
    const int row0 = blockIdx.x * BN + w * 16 + g;

    // ---- prefetch experts 0 and 1 (groups 0, 1) ----
    #pragma unroll
    for (int p = 0; p < 2; ++p) {
        uint32_t dst = smem_u32(smem + p * TILE_BYTES);
        const char* src = (const char*)(g_b + (size_t)p * 8192);
        #pragma unroll
        for (int i = 0; i < 8; ++i) {
            int o = (tid + i * 256) * 16;
            cp16(dst + o, src + o);
        }
        CP_COMMIT();
    }

    // ---- A fragments (hi/lo bf16 split), one-time gmem read; reused for all experts ----
    uint32_t Ahi[4][4], Alo[4][4];
    #pragma unroll
    for (int ks = 0; ks < 4; ++ks) {
        #pragma unroll
        for (int h = 0; h < 2; ++h) {
            int d = ks * 16 + q * 2 + h * 8;
            float2 v0 = __ldg((const float2*)(x + (size_t)row0 * KD + d));
            float2 v1 = __ldg((const float2*)(x + (size_t)(row0 + 8) * KD + d));
            __nv_bfloat16 h00 = __float2bfloat16(v0.x), h01 = __float2bfloat16(v0.y);
            __nv_bfloat16 h10 = __float2bfloat16(v1.x), h11 = __float2bfloat16(v1.y);
            Ahi[ks][h * 2 + 0] = pack_bf(h00, h01);
            Ahi[ks][h * 2 + 1] = pack_bf(h10, h11);
            Alo[ks][h * 2 + 0] = pack_bf(__float2bfloat16(v0.x - __bfloat162float(h00)),
                                         __float2bfloat16(v0.y - __bfloat162float(h01)));
            Alo[ks][h * 2 + 1] = pack_bf(__float2bfloat16(v1.x - __bfloat162float(h10)),
                                         __float2bfloat16(v1.y - __bfloat162float(h11)));
        }
    }

    float res0 = 0.f, res1 = 0.f;
    int cb = 0, pb = 2;   // consume-buffer, prefetch-buffer indices (mod 3)

    #pragma unroll 1
    for (int k = 0; k < KK; ++k) {
        // tile k was requested 2 experts ago -> wait is nearly always immediate
        if (k == KK - 1) { CP_WAIT(0); } else { CP_WAIT(1); }
        __syncthreads();   // all warps done reading buffer pb (consumed at k-1)

        if (k + 2 < KK) {  // prefetch expert k+2 into the freed buffer
            uint32_t dst = smem_u32(smem + pb * TILE_BYTES);
            const char* src = (const char*)(g_b + (size_t)(k + 2) * 8192);
            #pragma unroll
            for (int i = 0; i < 8; ++i) {
                int o = (tid + i * 256) * 16;
                cp16(dst + o, src + o);
            }
            CP_COMMIT();
        }

        const char* ab = smem + cb * TILE_BYTES;
        const float* bk = b + k * KM;
        float s0 = 0.f, s1 = 0.f;

        #pragma unroll
        for (int ch = 0; ch < 4; ++ch) {
            float acc[4][4];
            #pragma unroll
            for (int mt = 0; mt < 4; ++mt)
                #pragma unroll
                for (int j = 0; j < 4; ++j) acc[mt][j] = 0.f;

            #pragma unroll
            for (int ks = 0; ks < 4; ++ks) {
                #pragma unroll
                for (int mt = 0; mt < 4; ++mt) {
                    // one LDS.128: hi-regs AND lo-regs of B for this (ks, mtile)
                    uint4 B = *(const uint4*)(ab + (size_t)((ks * 16 + ch * 4 + mt) * 32 + l) * 16);
                    mma16816(acc[mt], Ahi[ks], B.x, B.y);   // hi*hi
                    mma16816(acc[mt], Ahi[ks], B.z, B.w);   // hi*lo
                    mma16816(acc[mt], Alo[ks], B.x, B.y);   // lo*hi
                }
            }

            // fused epilogue for this 32-column chunk (no max-sub: scores bounded)
            #pragma unroll
            for (int mt = 0; mt < 4; ++mt) {
                int m0 = (ch * 4 + mt) * 8 + q * 2;
                float2 bb = __ldg((const float2*)(bk + m0));
                s0 += __expf(acc[mt][0] + bb.x);
                s0 += __expf(acc[mt][1] + bb.y);
                s1 += __expf(acc[mt][2] + bb.x);
                s1 += __expf(acc[mt][3] + bb.y);
            }
        }

        // reduce exp-sums across the 4 lanes (q bits) sharing each n-row
        s0 += __shfl_xor_sync(0xffffffffu, s0, 1);
        s0 += __shfl_xor_sync(0xffffffffu, s0, 2);
        s1 += __shfl_xor_sync(0xffffffffu, s1, 1);
        s1 += __shfl_xor_sync(0xffffffffu, s1, 2);

        float sv = __ldg(s + k);
        res0 = fmaf(sv, __logf(s0), res0);
        res1 = fmaf(sv, __logf(s1), res1);

        cb = (cb == 2) ? 0 : cb + 1;
        pb = (pb == 2) ? 0 : pb + 1;
    }

    if (q == 0) {
        out[row0]     = res0;
        out[row0 + 8] = res1;
    }
}

extern "C" void kernel_launch(void* const* d_in, const int* in_sizes, int n_in,
                              void* d_out, int out_size)
{
    const float* x = (const float*)d_in[0];   // [131072, 64]
    const float* s = (const float*)d_in[1];   // [16]
    const float* a = (const float*)d_in[2];   // [16, 128, 64]
    const float* b = (const float*)d_in[3];   // [16, 128]
    float* out = (float*)d_out;

    cudaFuncSetAttribute(madk5, cudaFuncAttributeMaxDynamicSharedMemorySize, DYN_SMEM);

    prep<<<KK * 8192 / 256, 256>>>(a);
    madk5<<<KN / BN, 256, DYN_SMEM>>>(x, s, b, out);
}

// round 6
// speedup vs baseline: 1.2508x; 1.0090x over previous
#include <cuda_runtime.h>
#include <cuda_bf16.h>
#include <cstdint>

#define KN 131072
#define KK 16
#define KM 128
#define KD 64
#define BN 128   // n-rows per CTA (8 warps x 16 rows)

// Pre-split, fragment-arranged 'a':
// u32 index = (((k*4 + ks)*16 + mt)*32 + lane)*4 + c
//   c0,c1 = hi-split B regs, c2,c3 = lo-split B regs  (one uint4 per (k,ks,mt,lane))
__device__ __align__(16) uint32_t g_b[KK * 8192];   // 512 KB, L2-resident

__device__ __forceinline__ uint32_t pack_bf(__nv_bfloat16 a, __nv_bfloat16 b) {
    return (uint32_t)__bfloat16_as_ushort(a) | ((uint32_t)__bfloat16_as_ushort(b) << 16);
}

__global__ void prep(const float* __restrict__ a) {
    int idx = blockIdx.x * 256 + threadIdx.x;   // 0 .. 131071
    int c  = idx & 3;
    int l  = (idx >> 2) & 31;
    int mt = (idx >> 7) & 15;
    int ks = (idx >> 11) & 3;
    int k  = idx >> 13;
    int r  = c & 1, sp = c >> 1;
    int m  = mt * 8 + (l >> 2);
    int d0 = ks * 16 + (l & 3) * 2 + r * 8;
    const float* am = a + ((size_t)k * KM + m) * KD + d0;
    float v0 = am[0], v1 = am[1];
    __nv_bfloat16 h0 = __float2bfloat16(v0), h1 = __float2bfloat16(v1);
    uint32_t o;
    if (sp == 0) {
        o = pack_bf(h0, h1);
    } else {
        o = pack_bf(__float2bfloat16(v0 - __bfloat162float(h0)),
                    __float2bfloat16(v1 - __bfloat162float(h1)));
    }
    g_b[idx] = o;
}

__device__ __forceinline__ void mma16816(float (&c)[4], const uint32_t (&A)[4],
                                         uint32_t b0, uint32_t b1) {
    asm volatile(
        "mma.sync.aligned.m16n8k16.row.col.f32.bf16.bf16.f32 "
        "{%0,%1,%2,%3}, {%4,%5,%6,%7}, {%8,%9}, {%0,%1,%2,%3};"
        : "+f"(c[0]), "+f"(c[1]), "+f"(c[2]), "+f"(c[3])
        : "r"(A[0]), "r"(A[1]), "r"(A[2]), "r"(A[3]), "r"(b0), "r"(b1));
}

// No smem, no barriers: warps free-run across experts so epilogue (MUFU)
// of one warp overlaps HMMA of others. 2 CTAs/SM keeps ~128 regs so the
// compiler can hoist many independent B LDG.128s (MLP hides L1/L2 latency).
__global__ __launch_bounds__(256, 2)
void madk6(const float* __restrict__ x, const float* __restrict__ s,
           const float* __restrict__ b, float* __restrict__ out)
{
    const int tid = threadIdx.x;
    const int w = tid >> 5, l = tid & 31;
    const int g = l >> 2, q = l & 3;
    const int row0 = blockIdx.x * BN + w * 16 + g;

    // ---- A fragments (hi/lo bf16 split), one-time gmem read; reused for all experts ----
    uint32_t Ahi[4][4], Alo[4][4];
    #pragma unroll
    for (int ks = 0; ks < 4; ++ks) {
        #pragma unroll
        for (int h = 0; h < 2; ++h) {
            int d = ks * 16 + q * 2 + h * 8;
            float2 v0 = __ldg((const float2*)(x + (size_t)row0 * KD + d));
            float2 v1 = __ldg((const float2*)(x + (size_t)(row0 + 8) * KD + d));
            __nv_bfloat16 h00 = __float2bfloat16(v0.x), h01 = __float2bfloat16(v0.y);
            __nv_bfloat16 h10 = __float2bfloat16(v1.x), h11 = __float2bfloat16(v1.y);
            Ahi[ks][h * 2 + 0] = pack_bf(h00, h01);
            Ahi[ks][h * 2 + 1] = pack_bf(h10, h11);
            Alo[ks][h * 2 + 0] = pack_bf(__float2bfloat16(v0.x - __bfloat162float(h00)),
                                         __float2bfloat16(v0.y - __bfloat162float(h01)));
            Alo[ks][h * 2 + 1] = pack_bf(__float2bfloat16(v1.x - __bfloat162float(h10)),
                                         __float2bfloat16(v1.y - __bfloat162float(h11)));
        }
    }

    float res0 = 0.f, res1 = 0.f;

    #pragma unroll 1
    for (int k = 0; k < KK; ++k) {
        const uint4* gb = (const uint4*)g_b + ((size_t)k * 4 * 16 * 32) + l;
        const float* bk = b + k * KM;
        float s0 = 0.f, s1 = 0.f;

        #pragma unroll
        for (int ch = 0; ch < 4; ++ch) {
            float acc[4][4];
            #pragma unroll
            for (int mt = 0; mt < 4; ++mt)
                #pragma unroll
                for (int j = 0; j < 4; ++j) acc[mt][j] = 0.f;

            // hoist all 16 B loads for this chunk first -> deep MLP, then MMA burst
            uint4 B[4][4];
            #pragma unroll
            for (int ks = 0; ks < 4; ++ks)
                #pragma unroll
                for (int mt = 0; mt < 4; ++mt)
                    B[ks][mt] = __ldg(gb + (size_t)(ks * 16 + ch * 4 + mt) * 32);

            #pragma unroll
            for (int ks = 0; ks < 4; ++ks) {
                #pragma unroll
                for (int mt = 0; mt < 4; ++mt) {
                    mma16816(acc[mt], Ahi[ks], B[ks][mt].x, B[ks][mt].y);   // hi*hi
                    mma16816(acc[mt], Ahi[ks], B[ks][mt].z, B[ks][mt].w);   // hi*lo
                    mma16816(acc[mt], Alo[ks], B[ks][mt].x, B[ks][mt].y);   // lo*hi
                }
            }

            // fused epilogue for this 32-column chunk (no max-sub: scores bounded)
            #pragma unroll
            for (int mt = 0; mt < 4; ++mt) {
                int m0 = (ch * 4 + mt) * 8 + q * 2;
                float2 bb = __ldg((const float2*)(bk + m0));
                s0 += __expf(acc[mt][0] + bb.x);
                s0 += __expf(acc[mt][1] + bb.y);
                s1 += __expf(acc[mt][2] + bb.x);
                s1 += __expf(acc[mt][3] + bb.y);
            }
        }

        // reduce exp-sums across the 4 lanes (q bits) sharing each n-row
        s0 += __shfl_xor_sync(0xffffffffu, s0, 1);
        s0 += __shfl_xor_sync(0xffffffffu, s0, 2);
        s1 += __shfl_xor_sync(0xffffffffu, s1, 1);
        s1 += __shfl_xor_sync(0xffffffffu, s1, 2);

        float sv = __ldg(s + k);
        res0 = fmaf(sv, __logf(s0), res0);
        res1 = fmaf(sv, __logf(s1), res1);
    }

    if (q == 0) {
        out[row0]     = res0;
        out[row0 + 8] = res1;
    }
}

extern "C" void kernel_launch(void* const* d_in, const int* in_sizes, int n_in,
                              void* d_out, int out_size)
{
    const float* x = (const float*)d_in[0];   // [131072, 64]
    const float* s = (const float*)d_in[1];   // [16]
    const float* a = (const float*)d_in[2];   // [16, 128, 64]
    const float* b = (const float*)d_in[3];   // [16, 128]
    float* out = (float*)d_out;

    prep<<<KK * 8192 / 256, 256>>>(a);
    madk6<<<KN / BN, 256>>>(x, s, b, out);
}

// round 7
// speedup vs baseline: 1.7438x; 1.3941x over previous
#include <cuda_runtime.h>
#include <cuda_fp16.h>
#include <cstdint>

#define KN 131072
#define KK 16
#define KM 128
#define KD 64
#define BN 128   // n-rows per CTA (8 warps x 16 rows)

#define LOG2E 1.4426950408889634f
#define LN2   0.6931471805599453f

// fp16 'a' (pre-scaled by log2e), fragment-arranged:
// u32 index = (((k*4 + ks)*16 + mt)*32 + lane)*2 + r   (r = B-operand reg 0/1)
__device__ __align__(16) uint32_t g_b[KK * 4096];   // 256 KB, L2-resident

__global__ void prep(const float* __restrict__ a) {
    int idx = blockIdx.x * 256 + threadIdx.x;   // 0 .. 65535
    int r  = idx & 1;
    int l  = (idx >> 1) & 31;
    int mt = (idx >> 6) & 15;
    int ks = (idx >> 10) & 3;
    int k  = idx >> 12;
    int m  = mt * 8 + (l >> 2);
    int d0 = ks * 16 + (l & 3) * 2 + r * 8;
    const float* am = a + ((size_t)k * KM + m) * KD + d0;
    __half2 h = __floats2half2_rn(am[0] * LOG2E, am[1] * LOG2E);
    g_b[idx] = *(const uint32_t*)&h;
}

__device__ __forceinline__ void mma16816(float (&c)[4], const uint32_t (&A)[4],
                                         uint32_t b0, uint32_t b1) {
    asm volatile(
        "mma.sync.aligned.m16n8k16.row.col.f32.f16.f16.f32 "
        "{%0,%1,%2,%3}, {%4,%5,%6,%7}, {%8,%9}, {%0,%1,%2,%3};"
        : "+f"(c[0]), "+f"(c[1]), "+f"(c[2]), "+f"(c[3])
        : "r"(A[0]), "r"(A[1]), "r"(A[2]), "r"(A[3]), "r"(b0), "r"(b1));
}
__device__ __forceinline__ uint32_t smem_u32(const void* p) {
    uint32_t a;
    asm("{ .reg .u64 t; cvta.to.shared.u64 t, %1; cvt.u32.u64 %0, t; }" : "=r"(a) : "l"(p));
    return a;
}
__device__ __forceinline__ void cp16(uint32_t s, const void* g) {
    asm volatile("cp.async.cg.shared.global [%0], [%1], 16;" :: "r"(s), "l"(g));
}
#define CP_COMMIT() asm volatile("cp.async.commit_group;" ::: "memory")
#define CP_WAIT(n)  asm volatile("cp.async.wait_group %0;" :: "n"(n) : "memory")
__device__ __forceinline__ float ex2f(float v) {
    float r; asm("ex2.approx.f32 %0, %1;" : "=f"(r) : "f"(v)); return r;
}
__device__ __forceinline__ float lg2f(float v) {
    float r; asm("lg2.approx.f32 %0, %1;" : "=f"(r) : "f"(v)); return r;
}
__device__ __forceinline__ uint32_t packh(float a, float b) {
    __half2 h = __floats2half2_rn(a, b);
    return *(const uint32_t*)&h;
}

#define TILE_BYTES 16384
#define DYN_SMEM   (3 * TILE_BYTES)   // 48 KB ring of a-tiles

__global__ __launch_bounds__(256, 2)
void madk7(const float* __restrict__ x, const float* __restrict__ s,
           const float* __restrict__ b, float* __restrict__ out)
{
    extern __shared__ __align__(16) char smem[];

    const int tid = threadIdx.x;
    const int w = tid >> 5, l = tid & 31;
    const int g = l >> 2, q = l & 3;
    const int row0 = blockIdx.x * BN + w * 16 + g;

    // ---- prefetch experts 0, 1 ----
    #pragma unroll
    for (int p = 0; p < 2; ++p) {
        uint32_t dst = smem_u32(smem + p * TILE_BYTES);
        const char* src = (const char*)(g_b + (size_t)p * 4096);
        #pragma unroll
        for (int i = 0; i < 4; ++i) {
            int o = (tid + i * 256) * 16;
            cp16(dst + o, src + o);
        }
        CP_COMMIT();
    }

    // ---- A fragments: x split into exact fp16 hi+lo pair; reused for all experts ----
    uint32_t Xh[4][4], Xl[4][4];
    #pragma unroll
    for (int ks = 0; ks < 4; ++ks) {
        #pragma unroll
        for (int h = 0; h < 2; ++h) {
            int d = ks * 16 + q * 2 + h * 8;
            float2 v0 = __ldg((const float2*)(x + (size_t)row0 * KD + d));
            float2 v1 = __ldg((const float2*)(x + (size_t)(row0 + 8) * KD + d));
            float h00 = __half2float(__float2half_rn(v0.x));
            float h01 = __half2float(__float2half_rn(v0.y));
            float h10 = __half2float(__float2half_rn(v1.x));
            float h11 = __half2float(__float2half_rn(v1.y));
            Xh[ks][h * 2 + 0] = packh(h00, h01);
            Xh[ks][h * 2 + 1] = packh(h10, h11);
            Xl[ks][h * 2 + 0] = packh(v0.x - h00, v0.y - h01);
            Xl[ks][h * 2 + 1] = packh(v1.x - h10, v1.y - h11);
        }
    }

    float res0 = 0.f, res1 = 0.f;
    int cb = 0, pb = 2;

    #pragma unroll 1
    for (int k = 0; k < KK; ++k) {
        if (k == KK - 1) { CP_WAIT(0); } else { CP_WAIT(1); }
        __syncthreads();

        if (k + 2 < KK) {
            uint32_t dst = smem_u32(smem + pb * TILE_BYTES);
            const char* src = (const char*)(g_b + (size_t)(k + 2) * 4096);
            #pragma unroll
            for (int i = 0; i < 4; ++i) {
                int o = (tid + i * 256) * 16;
                cp16(dst + o, src + o);
            }
            CP_COMMIT();
        }

        const char* ab = smem + cb * TILE_BYTES;
        const float* bk = b + k * KM;
        float s0 = 0.f, s1 = 0.f;

        #pragma unroll
        for (int ch = 0; ch < 4; ++ch) {
            float acc[4][4];
            #pragma unroll
            for (int mt = 0; mt < 4; ++mt)
                #pragma unroll
                for (int j = 0; j < 4; ++j) acc[mt][j] = 0.f;

            // hoist the 16 B loads (LDS.64) for MLP, then MMA burst
            uint2 B[4][4];
            #pragma unroll
            for (int ks = 0; ks < 4; ++ks)
                #pragma unroll
                for (int mt = 0; mt < 4; ++mt)
                    B[ks][mt] = *(const uint2*)(ab + (size_t)((ks * 16 + ch * 4 + mt) * 32 + l) * 8);

            #pragma unroll
            for (int ks = 0; ks < 4; ++ks) {
                #pragma unroll
                for (int mt = 0; mt < 4; ++mt) {
                    mma16816(acc[mt], Xh[ks], B[ks][mt].x, B[ks][mt].y);
                    mma16816(acc[mt], Xl[ks], B[ks][mt].x, B[ks][mt].y);
                }
            }

            // fused epilogue: scores are already in log2 domain (a pre-scaled by log2e)
            #pragma unroll
            for (int mt = 0; mt < 4; ++mt) {
                int m0 = (ch * 4 + mt) * 8 + q * 2;
                float2 bb = __ldg((const float2*)(bk + m0));
                float b0 = bb.x * LOG2E, b1 = bb.y * LOG2E;
                s0 += ex2f(acc[mt][0] + b0);
                s0 += ex2f(acc[mt][1] + b1);
                s1 += ex2f(acc[mt][2] + b0);
                s1 += ex2f(acc[mt][3] + b1);
            }
        }

        s0 += __shfl_xor_sync(0xffffffffu, s0, 1);
        s0 += __shfl_xor_sync(0xffffffffu, s0, 2);
        s1 += __shfl_xor_sync(0xffffffffu, s1, 1);
        s1 += __shfl_xor_sync(0xffffffffu, s1, 2);

        float sv = __ldg(s + k) * LN2;      // lse = log2(sum) * ln2
        res0 = fmaf(sv, lg2f(s0), res0);
        res1 = fmaf(sv, lg2f(s1), res1);

        cb = (cb == 2) ? 0 : cb + 1;
        pb = (pb == 2) ? 0 : pb + 1;
    }

    if (q == 0) {
        out[row0]     = res0;
        out[row0 + 8] = res1;
    }
}

extern "C" void kernel_launch(void* const* d_in, const int* in_sizes, int n_in,
                              void* d_out, int out_size)
{
    const float* x = (const float*)d_in[0];   // [131072, 64]
    const float* s = (const float*)d_in[1];   // [16]
    const float* a = (const float*)d_in[2];   // [16, 128, 64]
    const float* b = (const float*)d_in[3];   // [16, 128]
    float* out = (float*)d_out;

    cudaFuncSetAttribute(madk7, cudaFuncAttributeMaxDynamicSharedMemorySize, DYN_SMEM);

    prep<<<KK * 4096 / 256, 256>>>(a);
    madk7<<<KN / BN, 256, DYN_SMEM>>>(x, s, b, out);
}

// round 8
// speedup vs baseline: 2.4191x; 1.3873x over previous
#include <cuda_runtime.h>
#include <cuda_fp16.h>
#include <cstdint>

#define KN 131072
#define KK 16
#define KM 128
#define KD 64
#define BN 128   // n-rows per CTA (8 warps x 16 rows)

#define LOG2E 1.4426950408889634f
#define LN2   0.6931471805599453f

// fp16 'a' (pre-scaled by log2e), fragment-arranged:
// u32 index = (((k*4 + ks)*16 + mt)*32 + lane)*2 + r   (r = B-operand reg 0/1)
__device__ __align__(16) uint32_t g_b[KK * 4096];   // 256 KB, L2-resident

__global__ void prep(const float* __restrict__ a) {
    int idx = blockIdx.x * 256 + threadIdx.x;   // 0 .. 65535
    int r  = idx & 1;
    int l  = (idx >> 1) & 31;
    int mt = (idx >> 6) & 15;
    int ks = (idx >> 10) & 3;
    int k  = idx >> 12;
    int m  = mt * 8 + (l >> 2);
    int d0 = ks * 16 + (l & 3) * 2 + r * 8;
    const float* am = a + ((size_t)k * KM + m) * KD + d0;
    __half2 h = __floats2half2_rn(am[0] * LOG2E, am[1] * LOG2E);
    g_b[idx] = *(const uint32_t*)&h;
}

__device__ __forceinline__ void mma16816(float (&c)[4], const uint32_t (&A)[4],
                                         uint32_t b0, uint32_t b1) {
    asm volatile(
        "mma.sync.aligned.m16n8k16.row.col.f32.f16.f16.f32 "
        "{%0,%1,%2,%3}, {%4,%5,%6,%7}, {%8,%9}, {%0,%1,%2,%3};"
        : "+f"(c[0]), "+f"(c[1]), "+f"(c[2]), "+f"(c[3])
        : "r"(A[0]), "r"(A[1]), "r"(A[2]), "r"(A[3]), "r"(b0), "r"(b1));
}
__device__ __forceinline__ uint32_t smem_u32(const void* p) {
    uint32_t a;
    asm("{ .reg .u64 t; cvta.to.shared.u64 t, %1; cvt.u32.u64 %0, t; }" : "=r"(a) : "l"(p));
    return a;
}
__device__ __forceinline__ void cp16(uint32_t s, const void* g) {
    asm volatile("cp.async.cg.shared.global [%0], [%1], 16;" :: "r"(s), "l"(g));
}
#define CP_COMMIT() asm volatile("cp.async.commit_group;" ::: "memory")
#define CP_WAIT(n)  asm volatile("cp.async.wait_group %0;" :: "n"(n) : "memory")
__device__ __forceinline__ float ex2f(float v) {
    float r; asm("ex2.approx.f32 %0, %1;" : "=f"(r) : "f"(v)); return r;
}
__device__ __forceinline__ float lg2f(float v) {
    float r; asm("lg2.approx.f32 %0, %1;" : "=f"(r) : "f"(v)); return r;
}
__device__ __forceinline__ uint32_t packh(float a, float b) {
    __half2 h = __floats2half2_rn(a, b);
    return *(const uint32_t*)&h;
}

#define TILE_BYTES 16384
#define DYN_SMEM   (3 * TILE_BYTES)   // 48 KB ring of a-tiles

__global__ __launch_bounds__(256, 2)
void madk8(const float* __restrict__ x, const float* __restrict__ s,
           const float* __restrict__ b, float* __restrict__ out)
{
    extern __shared__ __align__(16) char smem[];

    const int tid = threadIdx.x;
    const int w = tid >> 5, l = tid & 31;
    const int g = l >> 2, q = l & 3;
    const int row0 = blockIdx.x * BN + w * 16 + g;

    // ---- prefetch experts 0, 1 ----
    #pragma unroll
    for (int p = 0; p < 2; ++p) {
        uint32_t dst = smem_u32(smem + p * TILE_BYTES);
        const char* src = (const char*)(g_b + (size_t)p * 4096);
        #pragma unroll
        for (int i = 0; i < 4; ++i) {
            int o = (tid + i * 256) * 16;
            cp16(dst + o, src + o);
        }
        CP_COMMIT();
    }

    // ---- A fragments: x rounded once to fp16; reused for all experts ----
    uint32_t X[4][4];
    #pragma unroll
    for (int ks = 0; ks < 4; ++ks) {
        #pragma unroll
        for (int h = 0; h < 2; ++h) {
            int d = ks * 16 + q * 2 + h * 8;
            float2 v0 = __ldg((const float2*)(x + (size_t)row0 * KD + d));
            float2 v1 = __ldg((const float2*)(x + (size_t)(row0 + 8) * KD + d));
            X[ks][h * 2 + 0] = packh(v0.x, v0.y);
            X[ks][h * 2 + 1] = packh(v1.x, v1.y);
        }
    }

    float res0 = 0.f, res1 = 0.f;
    int cb = 0, pb = 2;

    #pragma unroll 1
    for (int k = 0; k < KK; ++k) {
        if (k == KK - 1) { CP_WAIT(0); } else { CP_WAIT(1); }
        __syncthreads();

        if (k + 2 < KK) {
            uint32_t dst = smem_u32(smem + pb * TILE_BYTES);
            const char* src = (const char*)(g_b + (size_t)(k + 2) * 4096);
            #pragma unroll
            for (int i = 0; i < 4; ++i) {
                int o = (tid + i * 256) * 16;
                cp16(dst + o, src + o);
            }
            CP_COMMIT();
        }

        const char* ab = smem + cb * TILE_BYTES;
        const float* bk = b + k * KM;
        float s0 = 0.f, s1 = 0.f;

        #pragma unroll
        for (int ch = 0; ch < 4; ++ch) {
            // bias (scaled to log2 domain) becomes the MMA initial accumulator
            float acc[4][4];
            #pragma unroll
            for (int mt = 0; mt < 4; ++mt) {
                int m0 = (ch * 4 + mt) * 8 + q * 2;
                float2 bb = __ldg((const float2*)(bk + m0));
                float b0 = bb.x * LOG2E, b1 = bb.y * LOG2E;
                acc[mt][0] = b0; acc[mt][1] = b1;
                acc[mt][2] = b0; acc[mt][3] = b1;
            }

            // hoist the 16 B loads (LDS.64) for MLP, then MMA burst
            uint2 B[4][4];
            #pragma unroll
            for (int ks = 0; ks < 4; ++ks)
                #pragma unroll
                for (int mt = 0; mt < 4; ++mt)
                    B[ks][mt] = *(const uint2*)(ab + (size_t)((ks * 16 + ch * 4 + mt) * 32 + l) * 8);

            #pragma unroll
            for (int ks = 0; ks < 4; ++ks)
                #pragma unroll
                for (int mt = 0; mt < 4; ++mt)
                    mma16816(acc[mt], X[ks], B[ks][mt].x, B[ks][mt].y);

            // fused epilogue: acc already = (x@a + b)*log2e
            #pragma unroll
            for (int mt = 0; mt < 4; ++mt) {
                s0 += ex2f(acc[mt][0]);
                s0 += ex2f(acc[mt][1]);
                s1 += ex2f(acc[mt][2]);
                s1 += ex2f(acc[mt][3]);
            }
        }

        s0 += __shfl_xor_sync(0xffffffffu, s0, 1);
        s0 += __shfl_xor_sync(0xffffffffu, s0, 2);
        s1 += __shfl_xor_sync(0xffffffffu, s1, 1);
        s1 += __shfl_xor_sync(0xffffffffu, s1, 2);

        float sv = __ldg(s + k) * LN2;      // lse = log2(sum) * ln2
        res0 = fmaf(sv, lg2f(s0), res0);
        res1 = fmaf(sv, lg2f(s1), res1);

        cb = (cb == 2) ? 0 : cb + 1;
        pb = (pb == 2) ? 0 : pb + 1;
    }

    if (q == 0) {
        out[row0]     = res0;
        out[row0 + 8] = res1;
    }
}

extern "C" void kernel_launch(void* const* d_in, const int* in_sizes, int n_in,
                              void* d_out, int out_size)
{
    const float* x = (const float*)d_in[0];   // [131072, 64]
    const float* s = (const float*)d_in[1];   // [16]
    const float* a = (const float*)d_in[2];   // [16, 128, 64]
    const float* b = (const float*)d_in[3];   // [16, 128]
    float* out = (float*)d_out;

    cudaFuncSetAttribute(madk8, cudaFuncAttributeMaxDynamicSharedMemorySize, DYN_SMEM);

    prep<<<KK * 4096 / 256, 256>>>(a);
    madk8<<<KN / BN, 256, DYN_SMEM>>>(x, s, b, out);
}

// round 9
// speedup vs baseline: 2.8796x; 1.1904x over previous
#include <cuda_runtime.h>
#include <cuda_fp16.h>
#include <cstdint>

#define KN 131072
#define KK 16
#define KM 128
#define KD 64
#define BN 128   // n-rows per CTA (4 warps x 32 rows)

#define LOG2E 1.4426950408889634f
#define LN2   0.6931471805599453f

// fp16 'a' (pre-scaled by log2e), fragment-arranged:
// u32 index = (((k*4 + ks)*16 + mt)*32 + lane)*2 + r   (r = B-operand reg 0/1)
__device__ __align__(16) uint32_t g_b[KK * 4096];   // 256 KB, L2-resident
__device__ float g_bs[KK * KM];                     // b * log2e
__device__ float g_ss[KK];                          // s * ln2

__global__ void prep(const float* __restrict__ a) {
    int idx = blockIdx.x * 256 + threadIdx.x;   // 0 .. 65535
    int r  = idx & 1;
    int l  = (idx >> 1) & 31;
    int mt = (idx >> 6) & 15;
    int ks = (idx >> 10) & 3;
    int k  = idx >> 12;
    int m  = mt * 8 + (l >> 2);
    int d0 = ks * 16 + (l & 3) * 2 + r * 8;
    const float* am = a + ((size_t)k * KM + m) * KD + d0;
    __half2 h = __floats2half2_rn(am[0] * LOG2E, am[1] * LOG2E);
    g_b[idx] = *(const uint32_t*)&h;
}
__global__ void prep2(const float* __restrict__ b, const float* __restrict__ s) {
    int idx = blockIdx.x * 256 + threadIdx.x;   // 0 .. 2047
    g_bs[idx] = b[idx] * LOG2E;
    if (idx < KK) g_ss[idx] = s[idx] * LN2;
}

__device__ __forceinline__ void mma16816(float (&c)[4], const uint32_t (&A)[4],
                                         uint32_t b0, uint32_t b1) {
    asm volatile(
        "mma.sync.aligned.m16n8k16.row.col.f32.f16.f16.f32 "
        "{%0,%1,%2,%3}, {%4,%5,%6,%7}, {%8,%9}, {%0,%1,%2,%3};"
        : "+f"(c[0]), "+f"(c[1]), "+f"(c[2]), "+f"(c[3])
        : "r"(A[0]), "r"(A[1]), "r"(A[2]), "r"(A[3]), "r"(b0), "r"(b1));
}
__device__ __forceinline__ uint32_t smem_u32(const void* p) {
    uint32_t a;
    asm("{ .reg .u64 t; cvta.to.shared.u64 t, %1; cvt.u32.u64 %0, t; }" : "=r"(a) : "l"(p));
    return a;
}
__device__ __forceinline__ void cp16(uint32_t s, const void* g) {
    asm volatile("cp.async.cg.shared.global [%0], [%1], 16;" :: "r"(s), "l"(g));
}
#define CP_COMMIT() asm volatile("cp.async.commit_group;" ::: "memory")
#define CP_WAIT(n)  asm volatile("cp.async.wait_group %0;" :: "n"(n) : "memory")
__device__ __forceinline__ float ex2f(float v) {
    float r; asm("ex2.approx.f32 %0, %1;" : "=f"(r) : "f"(v)); return r;
}
__device__ __forceinline__ float lg2f(float v) {
    float r; asm("lg2.approx.f32 %0, %1;" : "=f"(r) : "f"(v)); return r;
}
__device__ __forceinline__ uint32_t packh(float a, float b) {
    __half2 h = __floats2half2_rn(a, b);
    return *(const uint32_t*)&h;
}

#define TILE_BYTES 16384
#define DYN_SMEM   (2 * TILE_BYTES)   // 32 KB double buffer

// 128 threads = 4 warps; each warp owns 32 n-rows (2 A fragments), so every
// B fragment load feeds TWO MMAs and all per-chunk addressing/bias work is
// amortized over twice the rows. 4 CTAs/SM (64K regs exactly).
__global__ __launch_bounds__(128, 4)
void madk9(const float* __restrict__ x, float* __restrict__ out)
{
    extern __shared__ __align__(16) char smem[];

    const int tid = threadIdx.x;
    const int w = tid >> 5, l = tid & 31;
    const int g = l >> 2, q = l & 3;
    const int row0 = blockIdx.x * BN + w * 32 + g;

    // ---- prefetch expert 0 ----
    {
        uint32_t dst = smem_u32(smem);
        const char* src = (const char*)g_b;
        #pragma unroll
        for (int i = 0; i < 8; ++i) {
            int o = (tid + i * 128) * 16;
            cp16(dst + o, src + o);
        }
        CP_COMMIT();
    }

    // ---- A fragments: two 16-row fragments (rows row0..+8, row0+16..+24) ----
    uint32_t X[2][4][4];
    #pragma unroll
    for (int p = 0; p < 2; ++p) {
        #pragma unroll
        for (int ks = 0; ks < 4; ++ks) {
            #pragma unroll
            for (int h = 0; h < 2; ++h) {
                int d = ks * 16 + q * 2 + h * 8;
                int r = row0 + p * 16;
                float2 v0 = __ldg((const float2*)(x + (size_t)r * KD + d));
                float2 v1 = __ldg((const float2*)(x + (size_t)(r + 8) * KD + d));
                X[p][ks][h * 2 + 0] = packh(v0.x, v0.y);
                X[p][ks][h * 2 + 1] = packh(v1.x, v1.y);
            }
        }
    }

    float res0 = 0.f, res1 = 0.f, res2 = 0.f, res3 = 0.f;

    #pragma unroll 1
    for (int k = 0; k < KK; ++k) {
        CP_WAIT(0);
        __syncthreads();   // tile k ready; all warps done reading buffer (k+1)&1

        if (k + 1 < KK) {
            uint32_t dst = smem_u32(smem + ((k + 1) & 1) * TILE_BYTES);
            const char* src = (const char*)(g_b + (size_t)(k + 1) * 4096);
            #pragma unroll
            for (int i = 0; i < 8; ++i) {
                int o = (tid + i * 128) * 16;
                cp16(dst + o, src + o);
            }
            CP_COMMIT();
        }

        const char* ab = smem + (k & 1) * TILE_BYTES;
        const float* bk = g_bs + k * KM;
        float s0 = 0.f, s1 = 0.f, s2 = 0.f, s3 = 0.f;

        #pragma unroll
        for (int ch = 0; ch < 4; ++ch) {
            // bias (already log2-scaled) as initial accumulator for both row pairs
            float acc0[4][4], acc1[4][4];
            #pragma unroll
            for (int mt = 0; mt < 4; ++mt) {
                int m0 = (ch * 4 + mt) * 8 + q * 2;
                float2 bb = __ldg((const float2*)(bk + m0));
                acc0[mt][0] = bb.x; acc0[mt][1] = bb.y;
                acc0[mt][2] = bb.x; acc0[mt][3] = bb.y;
                acc1[mt][0] = bb.x; acc1[mt][1] = bb.y;
                acc1[mt][2] = bb.x; acc1[mt][3] = bb.y;
            }

            // hoist 16 B loads (LDS.64) for MLP; each feeds 2 MMAs
            uint2 B[4][4];
            #pragma unroll
            for (int ks = 0; ks < 4; ++ks)
                #pragma unroll
                for (int mt = 0; mt < 4; ++mt)
                    B[ks][mt] = *(const uint2*)(ab + (size_t)((ks * 16 + ch * 4 + mt) * 32 + l) * 8);

            #pragma unroll
            for (int ks = 0; ks < 4; ++ks) {
                #pragma unroll
                for (int mt = 0; mt < 4; ++mt) {
                    mma16816(acc0[mt], X[0][ks], B[ks][mt].x, B[ks][mt].y);
                    mma16816(acc1[mt], X[1][ks], B[ks][mt].x, B[ks][mt].y);
                }
            }

            // fused epilogue: acc = (x@a + b)*log2e
            #pragma unroll
            for (int mt = 0; mt < 4; ++mt) {
                s0 += ex2f(acc0[mt][0]);
                s0 += ex2f(acc0[mt][1]);
                s1 += ex2f(acc0[mt][2]);
                s1 += ex2f(acc0[mt][3]);
                s2 += ex2f(acc1[mt][0]);
                s2 += ex2f(acc1[mt][1]);
                s3 += ex2f(acc1[mt][2]);
                s3 += ex2f(acc1[mt][3]);
            }
        }

        s0 += __shfl_xor_sync(0xffffffffu, s0, 1);
        s0 += __shfl_xor_sync(0xffffffffu, s0, 2);
        s1 += __shfl_xor_sync(0xffffffffu, s1, 1);
        s1 += __shfl_xor_sync(0xffffffffu, s1, 2);
        s2 += __shfl_xor_sync(0xffffffffu, s2, 1);
        s2 += __shfl_xor_sync(0xffffffffu, s2, 2);
        s3 += __shfl_xor_sync(0xffffffffu, s3, 1);
        s3 += __shfl_xor_sync(0xffffffffu, s3, 2);

        float sv = g_ss[k];                 // s * ln2
        res0 = fmaf(sv, lg2f(s0), res0);
        res1 = fmaf(sv, lg2f(s1), res1);
        res2 = fmaf(sv, lg2f(s2), res2);
        res3 = fmaf(sv, lg2f(s3), res3);
    }

    if (q == 0) {
        out[row0]      = res0;
        out[row0 + 8]  = res1;
        out[row0 + 16] = res2;
        out[row0 + 24] = res3;
    }
}

extern "C" void kernel_launch(void* const* d_in, const int* in_sizes, int n_in,
                              void* d_out, int out_size)
{
    const float* x = (const float*)d_in[0];   // [131072, 64]
    const float* s = (const float*)d_in[1];   // [16]
    const float* a = (const float*)d_in[2];   // [16, 128, 64]
    const float* b = (const float*)d_in[3];   // [16, 128]
    float* out = (float*)d_out;

    cudaFuncSetAttribute(madk9, cudaFuncAttributeMaxDynamicSharedMemorySize, DYN_SMEM);

    prep<<<KK * 4096 / 256, 256>>>(a);
    prep2<<<KK * KM / 256, 256>>>(b, s);
    madk9<<<KN / BN, 128, DYN_SMEM>>>(x, out);
}

// round 10
// speedup vs baseline: 3.1126x; 1.0809x over previous
#include <cuda_runtime.h>
#include <cuda_fp16.h>
#include <cstdint>

#define KN 131072
#define KK 16
#define KM 128
#define KD 64
#define BN 128   // n-rows per CTA (4 warps x 32 rows)

#define LOG2E 1.4426950408889634f
#define LN2   0.6931471805599453f

// Per-expert tile (16896 B): [0,16384) fp16 'a' fragments (log2e-scaled),
//   u32 index (((ks*8 + mp)*32 + lane)*4 + c), c = (mt&1)*2 + reg  (mt = mp*2 + (c>>1))
//   -> one uint4 per (ks, m-tile-pair, lane) = B regs for TWO m-tiles
// [16384,16896): bias row, 128 floats * log2e
#define TILE_BYTES 16896
__device__ __align__(16) unsigned char g_bt[KK * TILE_BYTES];   // 264 KB, L2-resident
__device__ float g_ss[KK];                                      // s * ln2

__global__ void prep(const float* __restrict__ a, const float* __restrict__ b,
                     const float* __restrict__ s) {
    int idx = blockIdx.x * 256 + threadIdx.x;
    if (idx < 65536) {
        int c  = idx & 3;
        int l  = (idx >> 2) & 31;
        int mp = (idx >> 7) & 7;
        int ks = (idx >> 10) & 3;
        int k  = idx >> 12;
        int mt = mp * 2 + (c >> 1);
        int r  = c & 1;
        int m  = mt * 8 + (l >> 2);
        int d0 = ks * 16 + (l & 3) * 2 + r * 8;
        const float* am = a + ((size_t)k * KM + m) * KD + d0;
        __half2 h = __floats2half2_rn(am[0] * LOG2E, am[1] * LOG2E);
        *(uint32_t*)(g_bt + (size_t)k * TILE_BYTES +
                     ((((ks * 8 + mp) * 32 + l) * 4 + c) << 2)) = *(const uint32_t*)&h;
    } else if (idx < 65536 + KK * KM) {
        int j = idx - 65536;
        int k = j >> 7, m = j & 127;
        *(float*)(g_bt + (size_t)k * TILE_BYTES + 16384 + (m << 2)) = b[j] * LOG2E;
        if (j < KK) g_ss[j] = s[j] * LN2;
    }
}

__device__ __forceinline__ void mma16816(float (&c)[4], const uint32_t (&A)[4],
                                         uint32_t b0, uint32_t b1) {
    asm volatile(
        "mma.sync.aligned.m16n8k16.row.col.f32.f16.f16.f32 "
        "{%0,%1,%2,%3}, {%4,%5,%6,%7}, {%8,%9}, {%0,%1,%2,%3};"
        : "+f"(c[0]), "+f"(c[1]), "+f"(c[2]), "+f"(c[3])
        : "r"(A[0]), "r"(A[1]), "r"(A[2]), "r"(A[3]), "r"(b0), "r"(b1));
}
__device__ __forceinline__ uint32_t smem_u32(const void* p) {
    uint32_t a;
    asm("{ .reg .u64 t; cvta.to.shared.u64 t, %1; cvt.u32.u64 %0, t; }" : "=r"(a) : "l"(p));
    return a;
}
__device__ __forceinline__ void cp16(uint32_t s, const void* g) {
    asm volatile("cp.async.cg.shared.global [%0], [%1], 16;" :: "r"(s), "l"(g));
}
#define CP_COMMIT() asm volatile("cp.async.commit_group;" ::: "memory")
#define CP_WAIT(n)  asm volatile("cp.async.wait_group %0;" :: "n"(n) : "memory")
__device__ __forceinline__ float ex2f(float v) {
    float r; asm("ex2.approx.f32 %0, %1;" : "=f"(r) : "f"(v)); return r;
}
__device__ __forceinline__ float lg2f(float v) {
    float r; asm("lg2.approx.f32 %0, %1;" : "=f"(r) : "f"(v)); return r;
}
__device__ __forceinline__ uint32_t packh(float a, float b) {
    __half2 h = __floats2half2_rn(a, b);
    return *(const uint32_t*)&h;
}

#define DYN_SMEM (2 * TILE_BYTES)   // 33792 B double buffer

// 128 threads = 4 warps; each warp owns 32 n-rows. B feed = 32 LDS.128 per
// warp-expert (each uint4 feeds 4 MMAs); bias rides in the tile via cp.async.
__global__ __launch_bounds__(128, 4)
void madk10(const float* __restrict__ x, float* __restrict__ out)
{
    extern __shared__ __align__(16) char smem[];

    const int tid = threadIdx.x;
    const int w = tid >> 5, l = tid & 31;
    const int g = l >> 2, q = l & 3;
    const int row0 = blockIdx.x * BN + w * 32 + g;

    // ---- prefetch expert 0 (1056 uint4s) ----
    {
        uint32_t dst = smem_u32(smem);
        const char* src = (const char*)g_bt;
        #pragma unroll
        for (int i = 0; i < 9; ++i) {
            int o = tid + i * 128;
            if (o < TILE_BYTES / 16) cp16(dst + o * 16, src + o * 16);
        }
        CP_COMMIT();
    }

    // ---- A fragments: two 16-row fragments ----
    uint32_t X[2][4][4];
    #pragma unroll
    for (int p = 0; p < 2; ++p) {
        #pragma unroll
        for (int ks = 0; ks < 4; ++ks) {
            #pragma unroll
            for (int h = 0; h < 2; ++h) {
                int d = ks * 16 + q * 2 + h * 8;
                int r = row0 + p * 16;
                float2 v0 = __ldg((const float2*)(x + (size_t)r * KD + d));
                float2 v1 = __ldg((const float2*)(x + (size_t)(r + 8) * KD + d));
                X[p][ks][h * 2 + 0] = packh(v0.x, v0.y);
                X[p][ks][h * 2 + 1] = packh(v1.x, v1.y);
            }
        }
    }

    float res0 = 0.f, res1 = 0.f, res2 = 0.f, res3 = 0.f;

    #pragma unroll 1
    for (int k = 0; k < KK; ++k) {
        CP_WAIT(0);
        __syncthreads();

        if (k + 1 < KK) {
            uint32_t dst = smem_u32(smem + ((k + 1) & 1) * TILE_BYTES);
            const char* src = (const char*)(g_bt + (size_t)(k + 1) * TILE_BYTES);
            #pragma unroll
            for (int i = 0; i < 9; ++i) {
                int o = tid + i * 128;
                if (o < TILE_BYTES / 16) cp16(dst + o * 16, src + o * 16);
            }
            CP_COMMIT();
        }

        const char* ab = smem + (k & 1) * TILE_BYTES;
        const char* abias = ab + 16384;
        float s0 = 0.f, s1 = 0.f, s2 = 0.f, s3 = 0.f;

        #pragma unroll
        for (int ch = 0; ch < 4; ++ch) {
            // bias (log2e-scaled, from smem broadcast) as initial accumulator
            float acc0[4][4], acc1[4][4];
            #pragma unroll
            for (int mt = 0; mt < 4; ++mt) {
                int m0 = (ch * 4 + mt) * 8 + q * 2;
                float2 bb = *(const float2*)(abias + m0 * 4);
                acc0[mt][0] = bb.x; acc0[mt][1] = bb.y;
                acc0[mt][2] = bb.x; acc0[mt][3] = bb.y;
                acc1[mt][0] = bb.x; acc1[mt][1] = bb.y;
                acc1[mt][2] = bb.x; acc1[mt][3] = bb.y;
            }

            // 8 LDS.128: each uint4 carries B regs for an m-tile PAIR -> feeds 4 MMAs
            uint4 B[4][2];
            #pragma unroll
            for (int ks = 0; ks < 4; ++ks)
                #pragma unroll
                for (int mp = 0; mp < 2; ++mp)
                    B[ks][mp] = *(const uint4*)(ab +
                        (size_t)(((ks * 8 + ch * 2 + mp) * 32 + l) << 4));

            #pragma unroll
            for (int ks = 0; ks < 4; ++ks) {
                #pragma unroll
                for (int mp = 0; mp < 2; ++mp) {
                    mma16816(acc0[mp * 2 + 0], X[0][ks], B[ks][mp].x, B[ks][mp].y);
                    mma16816(acc1[mp * 2 + 0], X[1][ks], B[ks][mp].x, B[ks][mp].y);
                    mma16816(acc0[mp * 2 + 1], X[0][ks], B[ks][mp].z, B[ks][mp].w);
                    mma16816(acc1[mp * 2 + 1], X[1][ks], B[ks][mp].z, B[ks][mp].w);
                }
            }

            // fused epilogue: acc = (x@a + b)*log2e
            #pragma unroll
            for (int mt = 0; mt < 4; ++mt) {
                s0 += ex2f(acc0[mt][0]);
                s0 += ex2f(acc0[mt][1]);
                s1 += ex2f(acc0[mt][2]);
                s1 += ex2f(acc0[mt][3]);
                s2 += ex2f(acc1[mt][0]);
                s2 += ex2f(acc1[mt][1]);
                s3 += ex2f(acc1[mt][2]);
                s3 += ex2f(acc1[mt][3]);
            }
        }

        s0 += __shfl_xor_sync(0xffffffffu, s0, 1);
        s0 += __shfl_xor_sync(0xffffffffu, s0, 2);
        s1 += __shfl_xor_sync(0xffffffffu, s1, 1);
        s1 += __shfl_xor_sync(0xffffffffu, s1, 2);
        s2 += __shfl_xor_sync(0xffffffffu, s2, 1);
        s2 += __shfl_xor_sync(0xffffffffu, s2, 2);
        s3 += __shfl_xor_sync(0xffffffffu, s3, 1);
        s3 += __shfl_xor_sync(0xffffffffu, s3, 2);

        float sv = g_ss[k];                 // s * ln2
        res0 = fmaf(sv, lg2f(s0), res0);
        res1 = fmaf(sv, lg2f(s1), res1);
        res2 = fmaf(sv, lg2f(s2), res2);
        res3 = fmaf(sv, lg2f(s3), res3);
    }

    if (q == 0) {
        out[row0]      = res0;
        out[row0 + 8]  = res1;
        out[row0 + 16] = res2;
        out[row0 + 24] = res3;
    }
}

extern "C" void kernel_launch(void* const* d_in, const int* in_sizes, int n_in,
                              void* d_out, int out_size)
{
    const float* x = (const float*)d_in[0];   // [131072, 64]
    const float* s = (const float*)d_in[1];   // [16]
    const float* a = (const float*)d_in[2];   // [16, 128, 64]
    const float* b = (const float*)d_in[3];   // [16, 128]
    float* out = (float*)d_out;

    cudaFuncSetAttribute(madk10, cudaFuncAttributeMaxDynamicSharedMemorySize, DYN_SMEM);

    prep<<<(65536 + KK * KM + 255) / 256, 256>>>(a, b, s);
    madk10<<<KN / BN, 128, DYN_SMEM>>>(x, out);
}